// round 2
// baseline (speedup 1.0000x reference)
#include <cuda_runtime.h>
#include <cstdint>

#define NSAMP 65536      // 2*B halves
#define BORIG 32768
#define TT    15

// Scratch: layer-0 outputs [branch][sample][t][dir*32+h], and final 64-dim states.
__device__ float g_l0[(size_t)2 * NSAMP * TT * 64];   // ~503 MB
__device__ float g_last[(size_t)2 * NSAMP * 64];      // ~33 MB

__device__ __forceinline__ float sigf(float x) {
    return __fdividef(1.0f, 1.0f + __expf(-x));
}
__device__ __forceinline__ float tanh_fast(float x) {
    float e = __expf(-2.0f * x);
    return __fdividef(1.0f - e, 1.0f + e);
}

// One LSTM cell update for 32 hidden units.
// sW: 128 rows (gate-major: i rows 0..31, f 32..63, g 64..95, o 96..127),
//     each row NV4 float4s = [W_input | W_hidden | bias | zero-pad].
// v:  input vector (NV4*4 floats, register-resident). c updated in place, new h -> hn.
// j-loop deliberately rolled: keeps code size / register pressure bounded.
// c/hn become small local arrays (~256B/thread) - negligible traffic vs FMA work.
template<int NV4>
__device__ __forceinline__ void cell_update(const float* __restrict__ sW,
                                            const float* v,
                                            float* c,
                                            float* hn)
{
#pragma unroll 1
    for (int j = 0; j < 32; ++j) {
        const float4* ri = reinterpret_cast<const float4*>(sW) + (j      ) * NV4;
        const float4* rf = reinterpret_cast<const float4*>(sW) + (j + 32 ) * NV4;
        const float4* rg = reinterpret_cast<const float4*>(sW) + (j + 64 ) * NV4;
        const float4* ro = reinterpret_cast<const float4*>(sW) + (j + 96 ) * NV4;
        float ai = 0.f, af = 0.f, ag = 0.f, ao = 0.f;
#pragma unroll
        for (int k = 0; k < NV4; ++k) {
            float4 wa = ri[k], wb = rf[k], wc = rg[k], wd = ro[k];
            float v0 = v[4*k], v1 = v[4*k+1], v2 = v[4*k+2], v3 = v[4*k+3];
            ai = fmaf(wa.x, v0, ai); ai = fmaf(wa.y, v1, ai);
            ai = fmaf(wa.z, v2, ai); ai = fmaf(wa.w, v3, ai);
            af = fmaf(wb.x, v0, af); af = fmaf(wb.y, v1, af);
            af = fmaf(wb.z, v2, af); af = fmaf(wb.w, v3, af);
            ag = fmaf(wc.x, v0, ag); ag = fmaf(wc.y, v1, ag);
            ag = fmaf(wc.z, v2, ag); ag = fmaf(wc.w, v3, ag);
            ao = fmaf(wd.x, v0, ao); ao = fmaf(wd.y, v1, ao);
            ao = fmaf(wd.z, v2, ao); ao = fmaf(wd.w, v3, ao);
        }
        float cn = sigf(af) * c[j] + sigf(ai) * tanh_fast(ag);
        c[j] = cn;
        hn[j] = sigf(ao) * tanh_fast(cn);
    }
}

// ---------------- Layer 0: D=4 input, both dirs, both branches ----------------
// Row layout: [Wih(4) | Whh(32) | b(1) | pad(3)] -> NV4 = 10
__global__ void __launch_bounds__(128) lstm_layer0(
    const float* __restrict__ pos,
    const float* __restrict__ lWih, const float* __restrict__ lWhh, const float* __restrict__ lb,
    const float* __restrict__ vWih, const float* __restrict__ vWhh, const float* __restrict__ vb)
{
    __shared__ __align__(16) float sW[128 * 40];
    const int d  = blockIdx.y;
    const int br = blockIdx.z;
    const float* Wih = (br ? vWih : lWih) + d * 128 * 4;
    const float* Whh = (br ? vWhh : lWhh) + d * 128 * 32;
    const float* bb  = (br ? vb   : lb  ) + d * 128;

    for (int idx = threadIdx.x; idx < 128 * 40; idx += 128) {
        int r = idx / 40, o = idx % 40;
        float val = 0.f;
        if (o < 4)        val = Wih[r * 4 + o];
        else if (o < 36)  val = Whh[r * 32 + (o - 4)];
        else if (o == 36) val = bb[r];
        sW[idx] = val;
    }
    __syncthreads();

    const unsigned s = blockIdx.x * 128u + threadIdx.x;
    const float* xb = pos + (s < BORIG ? (size_t)s * 120 : (size_t)(s - BORIG) * 120 + 60);

    float v[40];
    float c[32], hn[32];
#pragma unroll
    for (int i = 0; i < 40; ++i) v[i] = 0.f;
    v[36] = 1.0f;                     // bias lane
#pragma unroll 1
    for (int j = 0; j < 32; ++j) c[j] = 0.f;

    float* out_base = g_l0 + ((size_t)br * NSAMP + s) * (TT * 64) + d * 32;

    for (int step = 0; step < TT; ++step) {
        const int t = d ? (TT - 1 - step) : step;
        float4 xt = *reinterpret_cast<const float4*>(xb + t * 4);
        v[0] = xt.x; v[1] = xt.y; v[2] = xt.z; v[3] = xt.w;

        cell_update<10>(sW, v, c, hn);

        float4* dst = reinterpret_cast<float4*>(out_base + (size_t)t * 64);
#pragma unroll
        for (int q = 0; q < 8; ++q) {
            float4 p = make_float4(hn[4*q], hn[4*q+1], hn[4*q+2], hn[4*q+3]);
            v[4 + 4*q] = p.x; v[5 + 4*q] = p.y; v[6 + 4*q] = p.z; v[7 + 4*q] = p.w;
            dst[q] = p;
        }
    }
}

// ---------------- Layer 1: 64-dim input; fwd 15 steps + bwd single step --------
// Fwd row: [Wih(64) | Whh(32) | b(1) | pad(3)]  -> NV4 = 25  (128*100 floats)
// Bwd row: [Wih(64) | b(1) | pad(3)]            -> NV4 = 17  (128*68 floats, h=0 so no Whh)
__global__ void __launch_bounds__(128) lstm_layer1(
    const float* __restrict__ lWih, const float* __restrict__ lWhh, const float* __restrict__ lb,
    const float* __restrict__ vWih, const float* __restrict__ vWhh, const float* __restrict__ vb)
{
    extern __shared__ __align__(16) float dsm[];
    float* sWF = dsm;                 // 128*100
    float* sWB = dsm + 128 * 100;     // 128*68
    const int br = blockIdx.y;
    const float* Wih = br ? vWih : lWih;
    const float* Whh = br ? vWhh : lWhh;
    const float* bb  = br ? vb   : lb;

    for (int idx = threadIdx.x; idx < 128 * 100; idx += 128) {
        int r = idx / 100, o = idx % 100;
        float val = 0.f;
        if (o < 64)       val = Wih[r * 64 + o];
        else if (o < 96)  val = Whh[r * 32 + (o - 64)];
        else if (o == 96) val = bb[r];
        sWF[idx] = val;
    }
    for (int idx = threadIdx.x; idx < 128 * 68; idx += 128) {
        int r = idx / 68, o = idx % 68;
        float val = 0.f;
        if (o < 64)       val = Wih[128 * 64 + r * 64 + o];  // dir 1
        else if (o == 64) val = bb[128 + r];
        sWB[idx] = val;
    }
    __syncthreads();

    const unsigned s = blockIdx.x * 128u + threadIdx.x;
    const float* in_base = g_l0 + ((size_t)br * NSAMP + s) * (TT * 64);

    float v[100];
    float c[32], hn[32];
#pragma unroll
    for (int i = 64; i < 100; ++i) v[i] = 0.f;
    v[96] = 1.0f;
#pragma unroll 1
    for (int j = 0; j < 32; ++j) c[j] = 0.f;

    for (int t = 0; t < TT; ++t) {
        const float4* src = reinterpret_cast<const float4*>(in_base + (size_t)t * 64);
#pragma unroll
        for (int q = 0; q < 16; ++q) {
            float4 p = src[q];
            v[4*q] = p.x; v[4*q+1] = p.y; v[4*q+2] = p.z; v[4*q+3] = p.w;
        }
        cell_update<25>(sWF, v, c, hn);
#pragma unroll
        for (int j = 0; j < 32; ++j) v[64 + j] = hn[j];
    }

    float* outp = g_last + ((size_t)br * NSAMP + s) * 64;
    float4* o4 = reinterpret_cast<float4*>(outp);
#pragma unroll
    for (int q = 0; q < 8; ++q)
        o4[q] = make_float4(v[64+4*q], v[65+4*q], v[66+4*q], v[67+4*q]);

    // Backward single step: input = layer-0 row at t=14 (still in v[0..63]), h0=c0=0.
    v[64] = 1.0f; v[65] = 0.f; v[66] = 0.f; v[67] = 0.f;
#pragma unroll 1
    for (int j = 0; j < 32; ++j) c[j] = 0.f;
    cell_update<17>(sWB, v, c, hn);
#pragma unroll
    for (int q = 0; q < 8; ++q)
        o4[8 + q] = make_float4(hn[4*q], hn[4*q+1], hn[4*q+2], hn[4*q+3]);
}

// ---------------- Head: argmax masks + FC ----------------
__global__ void __launch_bounds__(128) head_kernel(
    const float* __restrict__ dir,
    const float* __restrict__ lW, const float* __restrict__ lbias,
    const float* __restrict__ vW, const float* __restrict__ vbias,
    float* __restrict__ out)
{
    const int b = blockIdx.x * 128 + threadIdx.x;
    if (b >= BORIG) return;

    const float* di = dir + (size_t)b * 6;
    int am = 0; float mv = di[0];
#pragma unroll
    for (int i = 1; i < 6; ++i) { float x = di[i]; if (x > mv) { mv = x; am = i; } }
    const float m_vor = (am == 1 || am == 4) ? 1.f : 0.f;
    const float m_r   = (am == 0 || am == 5) ? 1.f : 0.f;
    const float m_l   = (am == 2 || am == 3) ? 1.f : 0.f;

    const float* ll = g_last + (size_t)b * 64;
    const float* lr = g_last + (size_t)(b + BORIG) * 64;
    const float* vl = g_last + ((size_t)NSAMP + b) * 64;
    const float* vr = g_last + ((size_t)NSAMP + b + BORIG) * 64;

    float xr0 = lbias[0], xr1 = lbias[1], xl0 = lbias[0], xl1 = lbias[1];
#pragma unroll 1
    for (int k = 0; k < 64; ++k) {
        float w0 = lW[k], w1 = lW[64 + k];
        float a = lr[k], bb2 = ll[k];
        xr0 = fmaf(a, w0, xr0); xr1 = fmaf(a, w1, xr1);
        xl0 = fmaf(bb2, w0, xl0); xl1 = fmaf(bb2, w1, xl1);
    }
    float xv0 = vbias[0], xv1 = vbias[1];
#pragma unroll 1
    for (int k = 0; k < 64; ++k) {
        float a = vl[k];
        xv0 = fmaf(a, vW[k], xv0); xv1 = fmaf(a, vW[128 + k], xv1);
    }
#pragma unroll 1
    for (int k = 0; k < 64; ++k) {
        float a = vr[k];
        xv0 = fmaf(a, vW[64 + k], xv0); xv1 = fmaf(a, vW[192 + k], xv1);
    }
    out[2 * b]     = xr0 * m_r + xl0 * m_l + xv0 * m_vor;
    out[2 * b + 1] = xr1 * m_r + xl1 * m_l + xv1 * m_vor;
}

extern "C" void kernel_launch(void* const* d_in, const int* in_sizes, int n_in,
                              void* d_out, int out_size)
{
    (void)in_sizes; (void)n_in; (void)out_size;
    const float* dir    = (const float*)d_in[0];
    const float* pos    = (const float*)d_in[1];
    const float* lWih0  = (const float*)d_in[2];
    const float* lWhh0  = (const float*)d_in[3];
    const float* lb0    = (const float*)d_in[4];
    const float* lWih1  = (const float*)d_in[5];
    const float* lWhh1  = (const float*)d_in[6];
    const float* lb1    = (const float*)d_in[7];
    const float* vWih0  = (const float*)d_in[8];
    const float* vWhh0  = (const float*)d_in[9];
    const float* vb0    = (const float*)d_in[10];
    const float* vWih1  = (const float*)d_in[11];
    const float* vWhh1  = (const float*)d_in[12];
    const float* vb1    = (const float*)d_in[13];
    const float* lfcW   = (const float*)d_in[14];
    const float* lfcb   = (const float*)d_in[15];
    const float* vfcW   = (const float*)d_in[16];
    const float* vfcb   = (const float*)d_in[17];
    float* out = (float*)d_out;

    const int smem2 = (128 * 100 + 128 * 68) * 4;  // 86016 B
    cudaFuncSetAttribute(lstm_layer1, cudaFuncAttributeMaxDynamicSharedMemorySize, smem2);

    lstm_layer0<<<dim3(512, 2, 2), 128>>>(pos, lWih0, lWhh0, lb0, vWih0, vWhh0, vb0);
    lstm_layer1<<<dim3(512, 2), 128, smem2>>>(lWih1, lWhh1, lb1, vWih1, vWhh1, vb1);
    head_kernel<<<256, 128>>>(dir, lfcW, lfcb, vfcW, vfcb, out);
}

// round 3
// speedup vs baseline: 1.0408x; 1.0408x over previous
#include <cuda_runtime.h>
#include <cstdint>

#define NSAMP 65536      // 2*B halves
#define BORIG 32768
#define TT    15

typedef unsigned long long u64;

// Scratch, sample-minor (coalesced): g_l0[br][t][feature(64)][sample], g_last[br][feature(64)][sample]
__device__ float g_l0[(size_t)2 * TT * 64 * NSAMP];   // ~503 MB
__device__ float g_last[(size_t)2 * 64 * NSAMP];      // ~33 MB

// ---- packed f32x2 helpers ----
__device__ __forceinline__ u64 pack2(float lo, float hi) {
    u64 r;
    asm("mov.b64 %0, {%1, %2};" : "=l"(r) : "r"(__float_as_uint(lo)), "r"(__float_as_uint(hi)));
    return r;
}
__device__ __forceinline__ void unpack2(u64 a, float& lo, float& hi) {
    unsigned x, y;
    asm("mov.b64 {%0, %1}, %2;" : "=r"(x), "=r"(y) : "l"(a));
    lo = __uint_as_float(x); hi = __uint_as_float(y);
}
__device__ __forceinline__ void fma2(u64& d, u64 a, u64 b) {
    asm("fma.rn.f32x2 %0, %1, %2, %0;" : "+l"(d) : "l"(a), "l"(b));
}

__device__ __forceinline__ float sigf(float x) {
    return __fdividef(1.0f, 1.0f + __expf(-x));
}
__device__ __forceinline__ float tanh_fast(float x) {
    float e = __expf(-2.0f * x);
    return __fdividef(1.0f - e, 1.0f + e);
}

// One LSTM cell update for 32 hidden units using packed f32x2 MACs.
// sW: 128 gate rows (i:0..31, f:32..63, g:64..95, o:96..127), each row NU u64
//     k-pairs = [W_input | W_hidden | bias-pair | zero-pad], row is 16B-aligned.
// v2: NU packed input pairs (register-resident). c updated in place, new h -> hn.
// j-loop rolled: bounds code size / register pressure; c,hn spill to local (~256B, fine).
template<int NU>
__device__ __forceinline__ void cell2(const u64* __restrict__ sW,
                                      const u64* v2, float* c, float* hn)
{
#pragma unroll 1
    for (int j = 0; j < 32; ++j) {
        const ulonglong2* ri = reinterpret_cast<const ulonglong2*>(sW + (size_t)(j      ) * NU);
        const ulonglong2* rf = reinterpret_cast<const ulonglong2*>(sW + (size_t)(j + 32 ) * NU);
        const ulonglong2* rg = reinterpret_cast<const ulonglong2*>(sW + (size_t)(j + 64 ) * NU);
        const ulonglong2* ro = reinterpret_cast<const ulonglong2*>(sW + (size_t)(j + 96 ) * NU);
        u64 ai = 0, af = 0, ag = 0, ao = 0;   // packed (0,0)
#pragma unroll
        for (int k = 0; k < NU / 2; ++k) {
            ulonglong2 wa = ri[k], wb = rf[k], wc = rg[k], wd = ro[k];
            u64 v0 = v2[2 * k], v1 = v2[2 * k + 1];
            fma2(ai, wa.x, v0); fma2(ai, wa.y, v1);
            fma2(af, wb.x, v0); fma2(af, wb.y, v1);
            fma2(ag, wc.x, v0); fma2(ag, wc.y, v1);
            fma2(ao, wd.x, v0); fma2(ao, wd.y, v1);
        }
        float i0,i1,f0,f1,g0,g1,o0,o1;
        unpack2(ai,i0,i1); unpack2(af,f0,f1); unpack2(ag,g0,g1); unpack2(ao,o0,o1);
        float cn = sigf(f0 + f1) * c[j] + sigf(i0 + i1) * tanh_fast(g0 + g1);
        c[j] = cn;
        hn[j] = sigf(o0 + o1) * tanh_fast(cn);
    }
}

// ---------------- Layer 0: D=4 input, both dirs, both branches ----------------
// Row: [Wih(4) | Whh(32) | b,0 | 0,0] -> NU = 20 u64 (160B/row)
__global__ void __launch_bounds__(128) lstm_layer0(
    const float* __restrict__ pos,
    const float* __restrict__ lWih, const float* __restrict__ lWhh, const float* __restrict__ lb,
    const float* __restrict__ vWih, const float* __restrict__ vWhh, const float* __restrict__ vb)
{
    extern __shared__ __align__(16) float sm0[];
    float* sWf = sm0;               // 128*40 floats
    float* sx  = sm0 + 128 * 40;    // 128 samples * 60 floats
    const int d  = blockIdx.y;
    const int br = blockIdx.z;
    const float* Wih = (br ? vWih : lWih) + d * 128 * 4;
    const float* Whh = (br ? vWhh : lWhh) + d * 128 * 32;
    const float* bb  = (br ? vb   : lb  ) + d * 128;

    for (int idx = threadIdx.x; idx < 128 * 40; idx += 128) {
        int r = idx / 40, o = idx % 40;
        float val = 0.f;
        if (o < 4)        val = Wih[r * 4 + o];
        else if (o < 36)  val = Whh[r * 32 + (o - 4)];
        else if (o == 36) val = bb[r];
        sWf[idx] = val;
    }
    // Stage this block's 128 samples' position data (60 floats each) coalesced.
    const unsigned s0 = blockIdx.x * 128u;
    for (int idx = threadIdx.x; idx < 128 * 60; idx += 128) {
        int i = idx / 60, f = idx % 60;
        unsigned s = s0 + i;
        const float* xb = pos + (s < BORIG ? (size_t)s * 120 : (size_t)(s - BORIG) * 120 + 60);
        sx[idx] = xb[f];
    }
    __syncthreads();

    const u64* sW = reinterpret_cast<const u64*>(sWf);
    const unsigned s = s0 + threadIdx.x;
    const float* xr = sx + threadIdx.x * 60;   // 240B stride: odd float4 stride, low conflicts

    u64 v2[20];
    float c[32], hn[32];
#pragma unroll
    for (int i = 0; i < 20; ++i) v2[i] = 0;
    v2[18] = pack2(1.0f, 0.0f);                // bias lane
#pragma unroll 1
    for (int j = 0; j < 32; ++j) c[j] = 0.f;

    float* gout = g_l0 + ((size_t)br * TT * 64 + d * 32) * NSAMP + s;

    for (int step = 0; step < TT; ++step) {
        const int t = d ? (TT - 1 - step) : step;
        float4 xt = *reinterpret_cast<const float4*>(xr + t * 4);
        v2[0] = pack2(xt.x, xt.y);
        v2[1] = pack2(xt.z, xt.w);

        cell2<20>(sW, v2, c, hn);

        float* go = gout + (size_t)t * 64 * NSAMP;
#pragma unroll 1
        for (int j = 0; j < 32; ++j) go[(size_t)j * NSAMP] = hn[j];   // coalesced
#pragma unroll
        for (int q = 0; q < 16; ++q) v2[2 + q] = pack2(hn[2*q], hn[2*q+1]);
    }
}

// ---------------- Layer 1: 64-dim input; fwd 15 steps + bwd single step --------
// Fwd row: [Wih(64) | Whh(32) | b,0 | 0,0] -> NU = 50 (400B/row)
// Bwd row: [Wih(64) | b,0 | 0,0]           -> NU = 34 (272B/row, h0=0 so no Whh)
__global__ void __launch_bounds__(128) lstm_layer1(
    const float* __restrict__ lWih, const float* __restrict__ lWhh, const float* __restrict__ lb,
    const float* __restrict__ vWih, const float* __restrict__ vWhh, const float* __restrict__ vb)
{
    extern __shared__ __align__(16) float sm1[];
    float* sWFf = sm1;                // 128*100
    float* sWBf = sm1 + 128 * 100;    // 128*68
    const int br = blockIdx.y;
    const float* Wih = br ? vWih : lWih;
    const float* Whh = br ? vWhh : lWhh;
    const float* bb  = br ? vb   : lb;

    for (int idx = threadIdx.x; idx < 128 * 100; idx += 128) {
        int r = idx / 100, o = idx % 100;
        float val = 0.f;
        if (o < 64)       val = Wih[r * 64 + o];
        else if (o < 96)  val = Whh[r * 32 + (o - 64)];
        else if (o == 96) val = bb[r];
        sWFf[idx] = val;
    }
    for (int idx = threadIdx.x; idx < 128 * 68; idx += 128) {
        int r = idx / 68, o = idx % 68;
        float val = 0.f;
        if (o < 64)       val = Wih[128 * 64 + r * 64 + o];  // dir 1
        else if (o == 64) val = bb[128 + r];
        sWBf[idx] = val;
    }
    __syncthreads();

    const u64* sWF = reinterpret_cast<const u64*>(sWFf);
    const u64* sWB = reinterpret_cast<const u64*>(sWBf);
    const unsigned s = blockIdx.x * 128u + threadIdx.x;
    const float* gin = g_l0 + (size_t)br * TT * 64 * NSAMP + s;

    u64 v2[50];
    float c[32], hn[32];
#pragma unroll
    for (int i = 32; i < 50; ++i) v2[i] = 0;
    v2[48] = pack2(1.0f, 0.0f);
#pragma unroll 1
    for (int j = 0; j < 32; ++j) c[j] = 0.f;

    for (int t = 0; t < TT; ++t) {
        const float* gt = gin + (size_t)t * 64 * NSAMP;
#pragma unroll
        for (int q = 0; q < 32; ++q)      // 64 coalesced LDG.32
            v2[q] = pack2(gt[(size_t)(2*q) * NSAMP], gt[(size_t)(2*q+1) * NSAMP]);
        cell2<50>(sWF, v2, c, hn);
#pragma unroll
        for (int q = 0; q < 16; ++q) v2[32 + q] = pack2(hn[2*q], hn[2*q+1]);
    }

    float* gl = g_last + (size_t)br * 64 * NSAMP + s;
#pragma unroll 1
    for (int j = 0; j < 32; ++j) gl[(size_t)j * NSAMP] = hn[j];       // fwd half

    // Backward single step: input = layer-0 features at t=14 (still in v2[0..31]), h0=c0=0.
    v2[32] = pack2(1.0f, 0.0f);
    v2[33] = 0;
#pragma unroll 1
    for (int j = 0; j < 32; ++j) c[j] = 0.f;
    cell2<34>(sWB, v2, c, hn);
#pragma unroll 1
    for (int j = 0; j < 32; ++j) gl[(size_t)(32 + j) * NSAMP] = hn[j]; // bwd half
}

// ---------------- Head: argmax masks + FC ----------------
__global__ void __launch_bounds__(128) head_kernel(
    const float* __restrict__ dir,
    const float* __restrict__ lW, const float* __restrict__ lbias,
    const float* __restrict__ vW, const float* __restrict__ vbias,
    float* __restrict__ out)
{
    const int b = blockIdx.x * 128 + threadIdx.x;
    if (b >= BORIG) return;

    const float* di = dir + (size_t)b * 6;
    int am = 0; float mv = di[0];
#pragma unroll
    for (int i = 1; i < 6; ++i) { float x = di[i]; if (x > mv) { mv = x; am = i; } }
    const float m_vor = (am == 1 || am == 4) ? 1.f : 0.f;
    const float m_r   = (am == 0 || am == 5) ? 1.f : 0.f;
    const float m_l   = (am == 2 || am == 3) ? 1.f : 0.f;

    const float* ll = g_last + b;                              // lvl, left half
    const float* lr = g_last + b + BORIG;                      // lvl, right half
    const float* vl = g_last + (size_t)64 * NSAMP + b;         // vor, left
    const float* vr = g_last + (size_t)64 * NSAMP + b + BORIG; // vor, right

    float xr0 = lbias[0], xr1 = lbias[1], xl0 = lbias[0], xl1 = lbias[1];
#pragma unroll 1
    for (int k = 0; k < 64; ++k) {
        float w0 = lW[k], w1 = lW[64 + k];
        float a = lr[(size_t)k * NSAMP], bb2 = ll[(size_t)k * NSAMP];
        xr0 = fmaf(a, w0, xr0); xr1 = fmaf(a, w1, xr1);
        xl0 = fmaf(bb2, w0, xl0); xl1 = fmaf(bb2, w1, xl1);
    }
    float xv0 = vbias[0], xv1 = vbias[1];
#pragma unroll 1
    for (int k = 0; k < 64; ++k) {
        float a = vl[(size_t)k * NSAMP];
        xv0 = fmaf(a, vW[k], xv0); xv1 = fmaf(a, vW[128 + k], xv1);
    }
#pragma unroll 1
    for (int k = 0; k < 64; ++k) {
        float a = vr[(size_t)k * NSAMP];
        xv0 = fmaf(a, vW[64 + k], xv0); xv1 = fmaf(a, vW[192 + k], xv1);
    }
    out[2 * b]     = xr0 * m_r + xl0 * m_l + xv0 * m_vor;
    out[2 * b + 1] = xr1 * m_r + xl1 * m_l + xv1 * m_vor;
}

extern "C" void kernel_launch(void* const* d_in, const int* in_sizes, int n_in,
                              void* d_out, int out_size)
{
    (void)in_sizes; (void)n_in; (void)out_size;
    const float* dir    = (const float*)d_in[0];
    const float* pos    = (const float*)d_in[1];
    const float* lWih0  = (const float*)d_in[2];
    const float* lWhh0  = (const float*)d_in[3];
    const float* lb0    = (const float*)d_in[4];
    const float* lWih1  = (const float*)d_in[5];
    const float* lWhh1  = (const float*)d_in[6];
    const float* lb1    = (const float*)d_in[7];
    const float* vWih0  = (const float*)d_in[8];
    const float* vWhh0  = (const float*)d_in[9];
    const float* vb0    = (const float*)d_in[10];
    const float* vWih1  = (const float*)d_in[11];
    const float* vWhh1  = (const float*)d_in[12];
    const float* vb1    = (const float*)d_in[13];
    const float* lfcW   = (const float*)d_in[14];
    const float* lfcb   = (const float*)d_in[15];
    const float* vfcW   = (const float*)d_in[16];
    const float* vfcb   = (const float*)d_in[17];
    float* out = (float*)d_out;

    const int smem0 = (128 * 40 + 128 * 60) * 4;        // 51200 B
    const int smem1 = (128 * 100 + 128 * 68) * 4;       // 86016 B
    cudaFuncSetAttribute(lstm_layer0, cudaFuncAttributeMaxDynamicSharedMemorySize, smem0);
    cudaFuncSetAttribute(lstm_layer1, cudaFuncAttributeMaxDynamicSharedMemorySize, smem1);

    lstm_layer0<<<dim3(512, 2, 2), 128, smem0>>>(pos, lWih0, lWhh0, lb0, vWih0, vWhh0, vb0);
    lstm_layer1<<<dim3(512, 2), 128, smem1>>>(lWih1, lWhh1, lb1, vWih1, vWhh1, vb1);
    head_kernel<<<256, 128>>>(dir, lfcW, lfcb, vfcW, vfcb, out);
}

// round 4
// speedup vs baseline: 1.0421x; 1.0013x over previous
#include <cuda_runtime.h>
#include <cstdint>

#define NSAMP 65536      // 2*B halves
#define BORIG 32768
#define TT    15

typedef unsigned long long u64;

// Scratch, sample-minor (coalesced): g_l0[br][t][feature(64)][sample], g_last[br][feature(64)][sample]
__device__ float g_l0[(size_t)2 * TT * 64 * NSAMP];   // ~503 MB
__device__ float g_last[(size_t)2 * 64 * NSAMP];      // ~33 MB

// ---- packed f32x2 helpers ----
__device__ __forceinline__ u64 pack2(float lo, float hi) {
    u64 r;
    asm("mov.b64 %0, {%1, %2};" : "=l"(r) : "r"(__float_as_uint(lo)), "r"(__float_as_uint(hi)));
    return r;
}
__device__ __forceinline__ void unpack2(u64 a, float& lo, float& hi) {
    unsigned x, y;
    asm("mov.b64 {%0, %1}, %2;" : "=r"(x), "=r"(y) : "l"(a));
    lo = __uint_as_float(x); hi = __uint_as_float(y);
}
__device__ __forceinline__ void fma2(u64& d, u64 a, u64 b) {
    asm("fma.rn.f32x2 %0, %1, %2, %0;" : "+l"(d) : "l"(a), "l"(b));
}

__device__ __forceinline__ float sigf(float x) {
    return __fdividef(1.0f, 1.0f + __expf(-x));
}
__device__ __forceinline__ float tanh_fast(float x) {
    float e = __expf(-2.0f * x);
    return __fdividef(1.0f - e, 1.0f + e);
}

// One LSTM cell update for 32 hidden units using packed f32x2 MACs.
// sW: 128 gate rows (i:0..31, f:32..63, g:64..95, o:96..127), each row NU u64
//     k-pairs = [W_input | W_hidden | bias-pair | zero-pad], row is 16B-aligned.
// v2: NU packed input pairs (register-resident). c updated in place, new h -> hn.
// j-loop rolled: bounds code size / register pressure; c,hn spill to local (~256B, fine).
template<int NU>
__device__ __forceinline__ void cell2(const u64* __restrict__ sW,
                                      const u64* v2, float* c, float* hn)
{
#pragma unroll 1
    for (int j = 0; j < 32; ++j) {
        const ulonglong2* ri = reinterpret_cast<const ulonglong2*>(sW + (size_t)(j      ) * NU);
        const ulonglong2* rf = reinterpret_cast<const ulonglong2*>(sW + (size_t)(j + 32 ) * NU);
        const ulonglong2* rg = reinterpret_cast<const ulonglong2*>(sW + (size_t)(j + 64 ) * NU);
        const ulonglong2* ro = reinterpret_cast<const ulonglong2*>(sW + (size_t)(j + 96 ) * NU);
        u64 ai = 0, af = 0, ag = 0, ao = 0;   // packed (0,0)
#pragma unroll
        for (int k = 0; k < NU / 2; ++k) {
            ulonglong2 wa = ri[k], wb = rf[k], wc = rg[k], wd = ro[k];
            u64 v0 = v2[2 * k], v1 = v2[2 * k + 1];
            fma2(ai, wa.x, v0); fma2(ai, wa.y, v1);
            fma2(af, wb.x, v0); fma2(af, wb.y, v1);
            fma2(ag, wc.x, v0); fma2(ag, wc.y, v1);
            fma2(ao, wd.x, v0); fma2(ao, wd.y, v1);
        }
        float i0,i1,f0,f1,g0,g1,o0,o1;
        unpack2(ai,i0,i1); unpack2(af,f0,f1); unpack2(ag,g0,g1); unpack2(ao,o0,o1);
        float cn = sigf(f0 + f1) * c[j] + sigf(i0 + i1) * tanh_fast(g0 + g1);
        c[j] = cn;
        hn[j] = sigf(o0 + o1) * tanh_fast(cn);
    }
}

// ---------------- Layer 0: D=4 input, both dirs, both branches ----------------
// Row: [Wih(4) | Whh(32) | b,0 | 0,0] -> NU = 20 u64 (160B/row)
__global__ void __launch_bounds__(128) lstm_layer0(
    const float* __restrict__ pos,
    const float* __restrict__ lWih, const float* __restrict__ lWhh, const float* __restrict__ lb,
    const float* __restrict__ vWih, const float* __restrict__ vWhh, const float* __restrict__ vb)
{
    extern __shared__ __align__(16) float sm0[];
    float* sWf = sm0;               // 128*40 floats
    float* sx  = sm0 + 128 * 40;    // 128 samples * 60 floats
    const int d  = blockIdx.y;
    const int br = blockIdx.z;
    const float* Wih = (br ? vWih : lWih) + d * 128 * 4;
    const float* Whh = (br ? vWhh : lWhh) + d * 128 * 32;
    const float* bb  = (br ? vb   : lb  ) + d * 128;

    for (int idx = threadIdx.x; idx < 128 * 40; idx += 128) {
        int r = idx / 40, o = idx % 40;
        float val = 0.f;
        if (o < 4)        val = Wih[r * 4 + o];
        else if (o < 36)  val = Whh[r * 32 + (o - 4)];
        else if (o == 36) val = bb[r];
        sWf[idx] = val;
    }
    // Stage this block's 128 samples' position data (60 floats each) coalesced.
    const unsigned s0 = blockIdx.x * 128u;
    for (int idx = threadIdx.x; idx < 128 * 60; idx += 128) {
        int i = idx / 60, f = idx % 60;
        unsigned s = s0 + i;
        const float* xb = pos + (s < BORIG ? (size_t)s * 120 : (size_t)(s - BORIG) * 120 + 60);
        sx[idx] = xb[f];
    }
    __syncthreads();

    const u64* sW = reinterpret_cast<const u64*>(sWf);
    const unsigned s = s0 + threadIdx.x;
    const float* xr = sx + threadIdx.x * 60;   // 240B stride: odd float4 stride, low conflicts

    u64 v2[20];
    float c[32], hn[32];
#pragma unroll
    for (int i = 0; i < 20; ++i) v2[i] = 0;
    v2[18] = pack2(1.0f, 0.0f);                // bias lane
#pragma unroll 1
    for (int j = 0; j < 32; ++j) c[j] = 0.f;

    float* gout = g_l0 + ((size_t)br * TT * 64 + d * 32) * NSAMP + s;

    for (int step = 0; step < TT; ++step) {
        const int t = d ? (TT - 1 - step) : step;
        float4 xt = *reinterpret_cast<const float4*>(xr + t * 4);
        v2[0] = pack2(xt.x, xt.y);
        v2[1] = pack2(xt.z, xt.w);

        cell2<20>(sW, v2, c, hn);

        float* go = gout + (size_t)t * 64 * NSAMP;
#pragma unroll 1
        for (int j = 0; j < 32; ++j) go[(size_t)j * NSAMP] = hn[j];   // coalesced
#pragma unroll
        for (int q = 0; q < 16; ++q) v2[2 + q] = pack2(hn[2*q], hn[2*q+1]);
    }
}

// ---------------- Layer 1: 64-dim input; fwd 15 steps + bwd single step --------
// Fwd row: [Wih(64) | Whh(32) | b,0 | 0,0] -> NU = 50 (400B/row)
// Bwd row: [Wih(64) | b,0 | 0,0]           -> NU = 34 (272B/row, h0=0 so no Whh)
__global__ void __launch_bounds__(128) lstm_layer1(
    const float* __restrict__ lWih, const float* __restrict__ lWhh, const float* __restrict__ lb,
    const float* __restrict__ vWih, const float* __restrict__ vWhh, const float* __restrict__ vb)
{
    extern __shared__ __align__(16) float sm1[];
    float* sWFf = sm1;                // 128*100
    float* sWBf = sm1 + 128 * 100;    // 128*68
    const int br = blockIdx.y;
    const float* Wih = br ? vWih : lWih;
    const float* Whh = br ? vWhh : lWhh;
    const float* bb  = br ? vb   : lb;

    for (int idx = threadIdx.x; idx < 128 * 100; idx += 128) {
        int r = idx / 100, o = idx % 100;
        float val = 0.f;
        if (o < 64)       val = Wih[r * 64 + o];
        else if (o < 96)  val = Whh[r * 32 + (o - 64)];
        else if (o == 96) val = bb[r];
        sWFf[idx] = val;
    }
    for (int idx = threadIdx.x; idx < 128 * 68; idx += 128) {
        int r = idx / 68, o = idx % 68;
        float val = 0.f;
        if (o < 64)       val = Wih[128 * 64 + r * 64 + o];  // dir 1
        else if (o == 64) val = bb[128 + r];
        sWBf[idx] = val;
    }
    __syncthreads();

    const u64* sWF = reinterpret_cast<const u64*>(sWFf);
    const u64* sWB = reinterpret_cast<const u64*>(sWBf);
    const unsigned s = blockIdx.x * 128u + threadIdx.x;
    const float* gin = g_l0 + (size_t)br * TT * 64 * NSAMP + s;

    u64 v2[50];
    float c[32], hn[32];
#pragma unroll
    for (int i = 32; i < 50; ++i) v2[i] = 0;
    v2[48] = pack2(1.0f, 0.0f);
#pragma unroll 1
    for (int j = 0; j < 32; ++j) c[j] = 0.f;

    for (int t = 0; t < TT; ++t) {
        const float* gt = gin + (size_t)t * 64 * NSAMP;
#pragma unroll
        for (int q = 0; q < 32; ++q)      // 64 coalesced LDG.32
            v2[q] = pack2(gt[(size_t)(2*q) * NSAMP], gt[(size_t)(2*q+1) * NSAMP]);
        cell2<50>(sWF, v2, c, hn);
#pragma unroll
        for (int q = 0; q < 16; ++q) v2[32 + q] = pack2(hn[2*q], hn[2*q+1]);
    }

    float* gl = g_last + (size_t)br * 64 * NSAMP + s;
#pragma unroll 1
    for (int j = 0; j < 32; ++j) gl[(size_t)j * NSAMP] = hn[j];       // fwd half

    // Backward single step: input = layer-0 features at t=14 (still in v2[0..31]), h0=c0=0.
    v2[32] = pack2(1.0f, 0.0f);
    v2[33] = 0;
#pragma unroll 1
    for (int j = 0; j < 32; ++j) c[j] = 0.f;
    cell2<34>(sWB, v2, c, hn);
#pragma unroll 1
    for (int j = 0; j < 32; ++j) gl[(size_t)(32 + j) * NSAMP] = hn[j]; // bwd half
}

// ---------------- Head: argmax masks + FC ----------------
__global__ void __launch_bounds__(128) head_kernel(
    const float* __restrict__ dir,
    const float* __restrict__ lW, const float* __restrict__ lbias,
    const float* __restrict__ vW, const float* __restrict__ vbias,
    float* __restrict__ out)
{
    const int b = blockIdx.x * 128 + threadIdx.x;
    if (b >= BORIG) return;

    const float* di = dir + (size_t)b * 6;
    int am = 0; float mv = di[0];
#pragma unroll
    for (int i = 1; i < 6; ++i) { float x = di[i]; if (x > mv) { mv = x; am = i; } }
    const float m_vor = (am == 1 || am == 4) ? 1.f : 0.f;
    const float m_r   = (am == 0 || am == 5) ? 1.f : 0.f;
    const float m_l   = (am == 2 || am == 3) ? 1.f : 0.f;

    const float* ll = g_last + b;                              // lvl, left half
    const float* lr = g_last + b + BORIG;                      // lvl, right half
    const float* vl = g_last + (size_t)64 * NSAMP + b;         // vor, left
    const float* vr = g_last + (size_t)64 * NSAMP + b + BORIG; // vor, right

    float xr0 = lbias[0], xr1 = lbias[1], xl0 = lbias[0], xl1 = lbias[1];
#pragma unroll 1
    for (int k = 0; k < 64; ++k) {
        float w0 = lW[k], w1 = lW[64 + k];
        float a = lr[(size_t)k * NSAMP], bb2 = ll[(size_t)k * NSAMP];
        xr0 = fmaf(a, w0, xr0); xr1 = fmaf(a, w1, xr1);
        xl0 = fmaf(bb2, w0, xl0); xl1 = fmaf(bb2, w1, xl1);
    }
    float xv0 = vbias[0], xv1 = vbias[1];
#pragma unroll 1
    for (int k = 0; k < 64; ++k) {
        float a = vl[(size_t)k * NSAMP];
        xv0 = fmaf(a, vW[k], xv0); xv1 = fmaf(a, vW[128 + k], xv1);
    }
#pragma unroll 1
    for (int k = 0; k < 64; ++k) {
        float a = vr[(size_t)k * NSAMP];
        xv0 = fmaf(a, vW[64 + k], xv0); xv1 = fmaf(a, vW[192 + k], xv1);
    }
    out[2 * b]     = xr0 * m_r + xl0 * m_l + xv0 * m_vor;
    out[2 * b + 1] = xr1 * m_r + xl1 * m_l + xv1 * m_vor;
}

extern "C" void kernel_launch(void* const* d_in, const int* in_sizes, int n_in,
                              void* d_out, int out_size)
{
    (void)in_sizes; (void)n_in; (void)out_size;
    const float* dir    = (const float*)d_in[0];
    const float* pos    = (const float*)d_in[1];
    const float* lWih0  = (const float*)d_in[2];
    const float* lWhh0  = (const float*)d_in[3];
    const float* lb0    = (const float*)d_in[4];
    const float* lWih1  = (const float*)d_in[5];
    const float* lWhh1  = (const float*)d_in[6];
    const float* lb1    = (const float*)d_in[7];
    const float* vWih0  = (const float*)d_in[8];
    const float* vWhh0  = (const float*)d_in[9];
    const float* vb0    = (const float*)d_in[10];
    const float* vWih1  = (const float*)d_in[11];
    const float* vWhh1  = (const float*)d_in[12];
    const float* vb1    = (const float*)d_in[13];
    const float* lfcW   = (const float*)d_in[14];
    const float* lfcb   = (const float*)d_in[15];
    const float* vfcW   = (const float*)d_in[16];
    const float* vfcb   = (const float*)d_in[17];
    float* out = (float*)d_out;

    const int smem0 = (128 * 40 + 128 * 60) * 4;        // 51200 B
    const int smem1 = (128 * 100 + 128 * 68) * 4;       // 86016 B
    cudaFuncSetAttribute(lstm_layer0, cudaFuncAttributeMaxDynamicSharedMemorySize, smem0);
    cudaFuncSetAttribute(lstm_layer1, cudaFuncAttributeMaxDynamicSharedMemorySize, smem1);

    lstm_layer0<<<dim3(512, 2, 2), 128, smem0>>>(pos, lWih0, lWhh0, lb0, vWih0, vWhh0, vb0);
    lstm_layer1<<<dim3(512, 2), 128, smem1>>>(lWih1, lWhh1, lb1, vWih1, vWhh1, vb1);
    head_kernel<<<256, 128>>>(dir, lfcW, lfcb, vfcW, vfcb, out);
}

// round 5
// speedup vs baseline: 1.4716x; 1.4122x over previous
#include <cuda_runtime.h>
#include <cstdint>

#define NSAMP 65536      // 2*B halves
#define BORIG 32768
#define TT    15

typedef unsigned long long u64;

// Scratch (all sample-minor / coalesced).
// g_xT:  transposed input, u64 k-pairs: [(t*2+p)][sample]
// g_l0u: layer-0 output feature-pairs: [br][t][kp(32)][sample] as u64
// g_last: final states, float [br][feat(64)][sample]
__device__ u64   g_xT[(size_t)30 * NSAMP];                 // ~16 MB
__device__ u64   g_l0u[(size_t)2 * TT * 32 * NSAMP];       // ~503 MB
__device__ float g_last[(size_t)2 * 64 * NSAMP];           // ~33 MB

// ---- packed f32x2 helpers ----
__device__ __forceinline__ u64 pack2(float lo, float hi) {
    u64 r;
    asm("mov.b64 %0, {%1, %2};" : "=l"(r) : "r"(__float_as_uint(lo)), "r"(__float_as_uint(hi)));
    return r;
}
__device__ __forceinline__ void unpack2(u64 a, float& lo, float& hi) {
    unsigned x, y;
    asm("mov.b64 {%0, %1}, %2;" : "=r"(x), "=r"(y) : "l"(a));
    lo = __uint_as_float(x); hi = __uint_as_float(y);
}
__device__ __forceinline__ void fma2(u64& d, u64 a, u64 b) {
    asm("fma.rn.f32x2 %0, %1, %2, %0;" : "+l"(d) : "l"(a), "l"(b));
}
__device__ __forceinline__ float usum(u64 a) {
    float lo, hi; unpack2(a, lo, hi); return lo + hi;
}

__device__ __forceinline__ float sigf(float x) {
    return __fdividef(1.0f, 1.0f + __expf(-x));
}
__device__ __forceinline__ float tanh_fast(float x) {
    float e = __expf(-2.0f * x);
    return __fdividef(1.0f - e, 1.0f + e);
}

// ---------------- Input transpose: pos -> g_xT[(t*2+p)][sample] (u64 pairs) ----------------
__global__ void __launch_bounds__(128) k_transpose(const float* __restrict__ pos)
{
    __shared__ float sx[128 * 60];
    const unsigned s0 = blockIdx.x * 128u;
    for (int idx = threadIdx.x; idx < 128 * 60; idx += 128) {
        int i = idx / 60, f = idx % 60;
        unsigned s = s0 + i;
        sx[idx] = pos[s < BORIG ? (size_t)s * 120 + f : (size_t)(s - BORIG) * 120 + 60 + f];
    }
    __syncthreads();
    const int i = threadIdx.x;
    const unsigned s = s0 + i;
#pragma unroll
    for (int u = 0; u < 30; ++u) {
        int t = u >> 1, p = u & 1;
        g_xT[(size_t)u * NSAMP + s] = pack2(sx[i * 60 + t * 4 + p * 2],
                                            sx[i * 60 + t * 4 + p * 2 + 1]);
    }
}

// ---------------- Layer 0: D=4 input, N=4 samples/thread ----------------
// Weight rows (float view): [Wih(4) | Whh(32)] = 36 floats/row, gate-major rows
// i:0..31 f:32..63 g:64..95 o:96..127.  u64 kp view: kp0,1 = x pairs; kp2..17 = h pairs.
__global__ void __launch_bounds__(128) lstm_layer0(
    const float* __restrict__ lWih, const float* __restrict__ lWhh, const float* __restrict__ lb,
    const float* __restrict__ vWih, const float* __restrict__ vWhh, const float* __restrict__ vb)
{
    __shared__ __align__(16) float sWf[128 * 36];
    __shared__ float sB[128];
    const int d  = blockIdx.y;
    const int br = blockIdx.z;
    const float* Wih = (br ? vWih : lWih) + d * 128 * 4;
    const float* Whh = (br ? vWhh : lWhh) + d * 128 * 32;
    const float* bb  = (br ? vb   : lb  ) + d * 128;

    for (int idx = threadIdx.x; idx < 128 * 36; idx += 128) {
        int r = idx / 36, o = idx % 36;
        sWf[idx] = (o < 4) ? Wih[r * 4 + o] : Whh[r * 32 + (o - 4)];
    }
    for (int idx = threadIdx.x; idx < 128; idx += 128) sB[idx] = bb[idx];
    __syncthreads();

    const u64* sW = reinterpret_cast<const u64*>(sWf);
    const unsigned s0 = blockIdx.x * 512u + threadIdx.x;   // samples s0 + n*128, n=0..3

    u64 v2[4][18];                 // per-sample input pairs: [0,1]=x, [2..17]=h
    float c[4][32], hn[4][32];     // local (dynamic j) - ~1KB/thread
#pragma unroll
    for (int n = 0; n < 4; ++n)
#pragma unroll
        for (int k = 2; k < 18; ++k) v2[n][k] = 0;
#pragma unroll 1
    for (int j = 0; j < 32; ++j)
#pragma unroll
        for (int n = 0; n < 4; ++n) c[n][j] = 0.f;

    for (int step = 0; step < TT; ++step) {
        const int t = d ? (TT - 1 - step) : step;
#pragma unroll
        for (int n = 0; n < 4; ++n) {
            v2[n][0] = g_xT[(size_t)(t * 2    ) * NSAMP + s0 + n * 128];
            v2[n][1] = g_xT[(size_t)(t * 2 + 1) * NSAMP + s0 + n * 128];
        }

#pragma unroll 1
        for (int j = 0; j < 32; ++j) {
            u64 acc[4][4];         // [gate][sample]
#pragma unroll
            for (int g = 0; g < 4; ++g)
#pragma unroll
                for (int n = 0; n < 4; ++n) acc[g][n] = 0;
#pragma unroll
            for (int g = 0; g < 4; ++g) {
                const ulonglong2* row = reinterpret_cast<const ulonglong2*>(sW + (size_t)(j + 32 * g) * 18);
#pragma unroll
                for (int k2 = 0; k2 < 9; ++k2) {
                    ulonglong2 w = row[k2];
#pragma unroll
                    for (int n = 0; n < 4; ++n) {
                        fma2(acc[g][n], w.x, v2[n][2 * k2]);
                        fma2(acc[g][n], w.y, v2[n][2 * k2 + 1]);
                    }
                }
            }
            float bi = sB[j], bf = sB[j + 32], bg = sB[j + 64], bo = sB[j + 96];
#pragma unroll
            for (int n = 0; n < 4; ++n) {
                float iv = usum(acc[0][n]) + bi;
                float fv = usum(acc[1][n]) + bf;
                float gv = usum(acc[2][n]) + bg;
                float ov = usum(acc[3][n]) + bo;
                float cn = sigf(fv) * c[n][j] + sigf(iv) * tanh_fast(gv);
                c[n][j] = cn;
                hn[n][j] = sigf(ov) * tanh_fast(cn);
            }
        }

        // recycle h into v2 and store feature-pairs (coalesced STG.64)
        u64* gb = g_l0u + ((size_t)(br * TT + t) * 32 + d * 16) * NSAMP;
#pragma unroll
        for (int q = 0; q < 16; ++q) {
#pragma unroll
            for (int n = 0; n < 4; ++n) {
                u64 hp = pack2(hn[n][2 * q], hn[n][2 * q + 1]);
                v2[n][2 + q] = hp;
                gb[(size_t)q * NSAMP + s0 + n * 128] = hp;
            }
        }
    }
}

// ---------------- Layer 1: N=2 samples/thread; fwd 15 steps + bwd single step --------
// Fwd row (float): [Wih(64) | Whh(32)] = 96 -> 48 u64 kp/row.
// Bwd row (float): [Wih(64)] = 64 -> 32 kp/row (h0=0). Biases separate.
template<int NKP>
__device__ __forceinline__ void cell1(const u64* __restrict__ sW, const float* __restrict__ sB,
                                      const u64* vA, const u64* vB,
                                      float* cA, float* cB, float* hA, float* hB)
{
#pragma unroll 1
    for (int j = 0; j < 32; ++j) {
        u64 aA[4], aB[4];
#pragma unroll
        for (int g = 0; g < 4; ++g) { aA[g] = 0; aB[g] = 0; }
#pragma unroll
        for (int g = 0; g < 4; ++g) {
            const ulonglong2* row = reinterpret_cast<const ulonglong2*>(sW + (size_t)(j + 32 * g) * NKP);
#pragma unroll
            for (int k2 = 0; k2 < NKP / 2; ++k2) {
                ulonglong2 w = row[k2];
                fma2(aA[g], w.x, vA[2 * k2]); fma2(aA[g], w.y, vA[2 * k2 + 1]);
                fma2(aB[g], w.x, vB[2 * k2]); fma2(aB[g], w.y, vB[2 * k2 + 1]);
            }
        }
        float bi = sB[j], bf = sB[j + 32], bg = sB[j + 64], bo = sB[j + 96];
        {
            float iv = usum(aA[0]) + bi, fv = usum(aA[1]) + bf;
            float gv = usum(aA[2]) + bg, ov = usum(aA[3]) + bo;
            float cn = sigf(fv) * cA[j] + sigf(iv) * tanh_fast(gv);
            cA[j] = cn; hA[j] = sigf(ov) * tanh_fast(cn);
        }
        {
            float iv = usum(aB[0]) + bi, fv = usum(aB[1]) + bf;
            float gv = usum(aB[2]) + bg, ov = usum(aB[3]) + bo;
            float cn = sigf(fv) * cB[j] + sigf(iv) * tanh_fast(gv);
            cB[j] = cn; hB[j] = sigf(ov) * tanh_fast(cn);
        }
    }
}

__global__ void __launch_bounds__(128) lstm_layer1(
    const float* __restrict__ lWih, const float* __restrict__ lWhh, const float* __restrict__ lb,
    const float* __restrict__ vWih, const float* __restrict__ vWhh, const float* __restrict__ vb)
{
    extern __shared__ __align__(16) float sm1[];
    float* sWFf = sm1;                       // 128*96
    float* sWBf = sm1 + 128 * 96;            // 128*64
    float* sBF  = sWBf + 128 * 64;           // 128
    float* sBB  = sBF + 128;                 // 128
    const int br = blockIdx.y;
    const float* Wih = br ? vWih : lWih;
    const float* Whh = br ? vWhh : lWhh;
    const float* bb  = br ? vb   : lb;

    for (int idx = threadIdx.x; idx < 128 * 96; idx += 128) {
        int r = idx / 96, o = idx % 96;
        sWFf[idx] = (o < 64) ? Wih[r * 64 + o] : Whh[r * 32 + (o - 64)];
    }
    for (int idx = threadIdx.x; idx < 128 * 64; idx += 128) {
        int r = idx / 64, o = idx % 64;
        sWBf[idx] = Wih[128 * 64 + r * 64 + o];       // dir 1
    }
    if (threadIdx.x < 128) { sBF[threadIdx.x] = bb[threadIdx.x]; sBB[threadIdx.x] = bb[128 + threadIdx.x]; }
    __syncthreads();

    const u64* sWF = reinterpret_cast<const u64*>(sWFf);
    const u64* sWB = reinterpret_cast<const u64*>(sWBf);
    const unsigned s = blockIdx.x * 256u + threadIdx.x * 2;   // samples s, s+1

    u64 vA[48], vB[48];
    float cA[32], cB[32], hA[32], hB[32];
#pragma unroll
    for (int k = 32; k < 48; ++k) { vA[k] = 0; vB[k] = 0; }
#pragma unroll 1
    for (int j = 0; j < 32; ++j) { cA[j] = 0.f; cB[j] = 0.f; }

    for (int t = 0; t < TT; ++t) {
        const u64* gb = g_l0u + (size_t)(br * TT + t) * 32 * NSAMP;
#pragma unroll
        for (int kp = 0; kp < 32; ++kp) {
            ulonglong2 xv = *reinterpret_cast<const ulonglong2*>(gb + (size_t)kp * NSAMP + s);
            vA[kp] = xv.x; vB[kp] = xv.y;
        }
        cell1<48>(sWF, sBF, vA, vB, cA, cB, hA, hB);
#pragma unroll
        for (int q = 0; q < 16; ++q) {
            vA[32 + q] = pack2(hA[2 * q], hA[2 * q + 1]);
            vB[32 + q] = pack2(hB[2 * q], hB[2 * q + 1]);
        }
    }

    // fwd final h -> g_last feats [0..31]
#pragma unroll 1
    for (int j = 0; j < 32; ++j)
        *reinterpret_cast<u64*>(g_last + (size_t)(br * 64 + j) * NSAMP + s) = pack2(hA[j], hB[j]);

    // bwd single step: input = t=14 features (still in vA/vB[0..31]), h0=c0=0
#pragma unroll 1
    for (int j = 0; j < 32; ++j) { cA[j] = 0.f; cB[j] = 0.f; }
    cell1<32>(sWB, sBB, vA, vB, cA, cB, hA, hB);
#pragma unroll 1
    for (int j = 0; j < 32; ++j)
        *reinterpret_cast<u64*>(g_last + (size_t)(br * 64 + 32 + j) * NSAMP + s) = pack2(hA[j], hB[j]);
}

// ---------------- Head: argmax masks + FC ----------------
__global__ void __launch_bounds__(128) head_kernel(
    const float* __restrict__ dir,
    const float* __restrict__ lW, const float* __restrict__ lbias,
    const float* __restrict__ vW, const float* __restrict__ vbias,
    float* __restrict__ out)
{
    const int b = blockIdx.x * 128 + threadIdx.x;
    if (b >= BORIG) return;

    const float* di = dir + (size_t)b * 6;
    int am = 0; float mv = di[0];
#pragma unroll
    for (int i = 1; i < 6; ++i) { float x = di[i]; if (x > mv) { mv = x; am = i; } }
    const float m_vor = (am == 1 || am == 4) ? 1.f : 0.f;
    const float m_r   = (am == 0 || am == 5) ? 1.f : 0.f;
    const float m_l   = (am == 2 || am == 3) ? 1.f : 0.f;

    const float* ll = g_last + b;                              // lvl, left half
    const float* lr = g_last + b + BORIG;                      // lvl, right half
    const float* vl = g_last + (size_t)64 * NSAMP + b;         // vor, left
    const float* vr = g_last + (size_t)64 * NSAMP + b + BORIG; // vor, right

    float xr0 = lbias[0], xr1 = lbias[1], xl0 = lbias[0], xl1 = lbias[1];
#pragma unroll 1
    for (int k = 0; k < 64; ++k) {
        float w0 = lW[k], w1 = lW[64 + k];
        float a = lr[(size_t)k * NSAMP], bb2 = ll[(size_t)k * NSAMP];
        xr0 = fmaf(a, w0, xr0); xr1 = fmaf(a, w1, xr1);
        xl0 = fmaf(bb2, w0, xl0); xl1 = fmaf(bb2, w1, xl1);
    }
    float xv0 = vbias[0], xv1 = vbias[1];
#pragma unroll 1
    for (int k = 0; k < 64; ++k) {
        float a = vl[(size_t)k * NSAMP];
        xv0 = fmaf(a, vW[k], xv0); xv1 = fmaf(a, vW[128 + k], xv1);
    }
#pragma unroll 1
    for (int k = 0; k < 64; ++k) {
        float a = vr[(size_t)k * NSAMP];
        xv0 = fmaf(a, vW[64 + k], xv0); xv1 = fmaf(a, vW[192 + k], xv1);
    }
    out[2 * b]     = xr0 * m_r + xl0 * m_l + xv0 * m_vor;
    out[2 * b + 1] = xr1 * m_r + xl1 * m_l + xv1 * m_vor;
}

extern "C" void kernel_launch(void* const* d_in, const int* in_sizes, int n_in,
                              void* d_out, int out_size)
{
    (void)in_sizes; (void)n_in; (void)out_size;
    const float* dir    = (const float*)d_in[0];
    const float* pos    = (const float*)d_in[1];
    const float* lWih0  = (const float*)d_in[2];
    const float* lWhh0  = (const float*)d_in[3];
    const float* lb0    = (const float*)d_in[4];
    const float* lWih1  = (const float*)d_in[5];
    const float* lWhh1  = (const float*)d_in[6];
    const float* lb1    = (const float*)d_in[7];
    const float* vWih0  = (const float*)d_in[8];
    const float* vWhh0  = (const float*)d_in[9];
    const float* vb0    = (const float*)d_in[10];
    const float* vWih1  = (const float*)d_in[11];
    const float* vWhh1  = (const float*)d_in[12];
    const float* vb1    = (const float*)d_in[13];
    const float* lfcW   = (const float*)d_in[14];
    const float* lfcb   = (const float*)d_in[15];
    const float* vfcW   = (const float*)d_in[16];
    const float* vfcb   = (const float*)d_in[17];
    float* out = (float*)d_out;

    const int smem1 = (128 * 96 + 128 * 64 + 256) * 4;   // 82944 B
    cudaFuncSetAttribute(lstm_layer1, cudaFuncAttributeMaxDynamicSharedMemorySize, smem1);

    k_transpose<<<NSAMP / 128, 128>>>(pos);
    lstm_layer0<<<dim3(NSAMP / 512, 2, 2), 128>>>(lWih0, lWhh0, lb0, vWih0, vWhh0, vb0);
    lstm_layer1<<<dim3(NSAMP / 256, 2), 128, smem1>>>(lWih1, lWhh1, lb1, vWih1, vWhh1, vb1);
    head_kernel<<<256, 128>>>(dir, lfcW, lfcb, vfcW, vfcb, out);
}

// round 6
// speedup vs baseline: 1.8358x; 1.2475x over previous
#include <cuda_runtime.h>
#include <cstdint>

#define NSAMP 65536      // 2*B halves
#define BORIG 32768
#define TT    15

typedef unsigned long long u64;

// Scratch (all sample-minor / coalesced).
__device__ u64   g_xT[(size_t)30 * NSAMP];                 // transposed input pairs
__device__ u64   g_l0u[(size_t)2 * TT * 32 * NSAMP];       // layer-0 output feature-pairs (~503 MB)
__device__ float g_last[(size_t)2 * 64 * NSAMP];           // final states (~33 MB)

// ---- packed f32x2 helpers ----
__device__ __forceinline__ u64 pack2(float lo, float hi) {
    u64 r;
    asm("mov.b64 %0, {%1, %2};" : "=l"(r) : "r"(__float_as_uint(lo)), "r"(__float_as_uint(hi)));
    return r;
}
__device__ __forceinline__ void unpack2(u64 a, float& lo, float& hi) {
    unsigned x, y;
    asm("mov.b64 {%0, %1}, %2;" : "=r"(x), "=r"(y) : "l"(a));
    lo = __uint_as_float(x); hi = __uint_as_float(y);
}
__device__ __forceinline__ void fma2(u64& d, u64 a, u64 b) {
    asm("fma.rn.f32x2 %0, %1, %2, %0;" : "+l"(d) : "l"(a), "l"(b));
}
__device__ __forceinline__ float usum(u64 a) {
    float lo, hi; unpack2(a, lo, hi); return lo + hi;
}

// ---- fast activations: single-MUFU tanh; sigmoid via tanh identity ----
__device__ __forceinline__ float tanhx(float x) {
    float r;
    asm("tanh.approx.f32 %0, %1;" : "=f"(r) : "f"(x));
    return r;
}
__device__ __forceinline__ float sigf(float x) {
    return fmaf(0.5f, tanhx(0.5f * x), 0.5f);
}

// ---------------- Input transpose: pos -> g_xT[(t*2+p)][sample] (u64 pairs) ----------------
__global__ void __launch_bounds__(128) k_transpose(const float* __restrict__ pos)
{
    __shared__ float sx[128 * 60];
    const unsigned s0 = blockIdx.x * 128u;
    for (int idx = threadIdx.x; idx < 128 * 60; idx += 128) {
        int i = idx / 60, f = idx % 60;
        unsigned s = s0 + i;
        sx[idx] = pos[s < BORIG ? (size_t)s * 120 + f : (size_t)(s - BORIG) * 120 + 60 + f];
    }
    __syncthreads();
    const int i = threadIdx.x;
    const unsigned s = s0 + i;
#pragma unroll
    for (int u = 0; u < 30; ++u) {
        int t = u >> 1, p = u & 1;
        g_xT[(size_t)u * NSAMP + s] = pack2(sx[i * 60 + t * 4 + p * 2],
                                            sx[i * 60 + t * 4 + p * 2 + 1]);
    }
}

// ---------------- Layer 0: D=4 input, N=4 samples/thread ----------------
__global__ void __launch_bounds__(128) lstm_layer0(
    const float* __restrict__ lWih, const float* __restrict__ lWhh, const float* __restrict__ lb,
    const float* __restrict__ vWih, const float* __restrict__ vWhh, const float* __restrict__ vb)
{
    __shared__ __align__(16) float sWf[128 * 36];
    __shared__ float sB[128];
    const int d  = blockIdx.y;
    const int br = blockIdx.z;
    const float* Wih = (br ? vWih : lWih) + d * 128 * 4;
    const float* Whh = (br ? vWhh : lWhh) + d * 128 * 32;
    const float* bb  = (br ? vb   : lb  ) + d * 128;

    for (int idx = threadIdx.x; idx < 128 * 36; idx += 128) {
        int r = idx / 36, o = idx % 36;
        sWf[idx] = (o < 4) ? Wih[r * 4 + o] : Whh[r * 32 + (o - 4)];
    }
    sB[threadIdx.x] = bb[threadIdx.x];
    __syncthreads();

    const u64* sW = reinterpret_cast<const u64*>(sWf);
    const unsigned s0 = blockIdx.x * 512u + threadIdx.x;   // samples s0 + n*128

    u64 v2[4][18];                 // [0,1]=x pairs, [2..17]=h pairs
    float c[4][32], hn[4][32];
#pragma unroll
    for (int n = 0; n < 4; ++n)
#pragma unroll
        for (int k = 2; k < 18; ++k) v2[n][k] = 0;
#pragma unroll 1
    for (int j = 0; j < 32; ++j)
#pragma unroll
        for (int n = 0; n < 4; ++n) c[n][j] = 0.f;

    for (int step = 0; step < TT; ++step) {
        const int t = d ? (TT - 1 - step) : step;
#pragma unroll
        for (int n = 0; n < 4; ++n) {
            v2[n][0] = g_xT[(size_t)(t * 2    ) * NSAMP + s0 + n * 128];
            v2[n][1] = g_xT[(size_t)(t * 2 + 1) * NSAMP + s0 + n * 128];
        }

#pragma unroll 1
        for (int j = 0; j < 32; ++j) {
            u64 acc[4][4];
#pragma unroll
            for (int g = 0; g < 4; ++g)
#pragma unroll
                for (int n = 0; n < 4; ++n) acc[g][n] = 0;
#pragma unroll
            for (int g = 0; g < 4; ++g) {
                const ulonglong2* row = reinterpret_cast<const ulonglong2*>(sW + (size_t)(j + 32 * g) * 18);
#pragma unroll
                for (int k2 = 0; k2 < 9; ++k2) {
                    ulonglong2 w = row[k2];
#pragma unroll
                    for (int n = 0; n < 4; ++n) {
                        fma2(acc[g][n], w.x, v2[n][2 * k2]);
                        fma2(acc[g][n], w.y, v2[n][2 * k2 + 1]);
                    }
                }
            }
            float bi = sB[j], bf = sB[j + 32], bg = sB[j + 64], bo = sB[j + 96];
#pragma unroll
            for (int n = 0; n < 4; ++n) {
                float iv = usum(acc[0][n]) + bi;
                float fv = usum(acc[1][n]) + bf;
                float gv = usum(acc[2][n]) + bg;
                float ov = usum(acc[3][n]) + bo;
                float cn = sigf(fv) * c[n][j] + sigf(iv) * tanhx(gv);
                c[n][j] = cn;
                hn[n][j] = sigf(ov) * tanhx(cn);
            }
        }

        u64* gb = g_l0u + ((size_t)(br * TT + t) * 32 + d * 16) * NSAMP;
#pragma unroll
        for (int q = 0; q < 16; ++q) {
#pragma unroll
            for (int n = 0; n < 4; ++n) {
                u64 hp = pack2(hn[n][2 * q], hn[n][2 * q + 1]);
                v2[n][2 + q] = hp;
                gb[(size_t)q * NSAMP + s0 + n * 128] = hp;
            }
        }
    }
}

// ---------------- Layer 1: N=2 samples/thread; fwd 15 steps + bwd single step --------
template<int NKP>
__device__ __forceinline__ void cell1(const u64* __restrict__ sW, const float* __restrict__ sB,
                                      const u64* vA, const u64* vB,
                                      float* cA, float* cB, float* hA, float* hB)
{
#pragma unroll 2
    for (int j = 0; j < 32; ++j) {
        u64 aA[4], aB[4];
#pragma unroll
        for (int g = 0; g < 4; ++g) { aA[g] = 0; aB[g] = 0; }
#pragma unroll
        for (int g = 0; g < 4; ++g) {
            const ulonglong2* row = reinterpret_cast<const ulonglong2*>(sW + (size_t)(j + 32 * g) * NKP);
#pragma unroll
            for (int k2 = 0; k2 < NKP / 2; ++k2) {
                ulonglong2 w = row[k2];
                fma2(aA[g], w.x, vA[2 * k2]); fma2(aA[g], w.y, vA[2 * k2 + 1]);
                fma2(aB[g], w.x, vB[2 * k2]); fma2(aB[g], w.y, vB[2 * k2 + 1]);
            }
        }
        float bi = sB[j], bf = sB[j + 32], bg = sB[j + 64], bo = sB[j + 96];
        {
            float iv = usum(aA[0]) + bi, fv = usum(aA[1]) + bf;
            float gv = usum(aA[2]) + bg, ov = usum(aA[3]) + bo;
            float cn = sigf(fv) * cA[j] + sigf(iv) * tanhx(gv);
            cA[j] = cn; hA[j] = sigf(ov) * tanhx(cn);
        }
        {
            float iv = usum(aB[0]) + bi, fv = usum(aB[1]) + bf;
            float gv = usum(aB[2]) + bg, ov = usum(aB[3]) + bo;
            float cn = sigf(fv) * cB[j] + sigf(iv) * tanhx(gv);
            cB[j] = cn; hB[j] = sigf(ov) * tanhx(cn);
        }
    }
}

__global__ void __launch_bounds__(128) lstm_layer1(
    const float* __restrict__ lWih, const float* __restrict__ lWhh, const float* __restrict__ lb,
    const float* __restrict__ vWih, const float* __restrict__ vWhh, const float* __restrict__ vb)
{
    extern __shared__ __align__(16) float sm1[];
    float* sWFf = sm1;                       // 128*96
    float* sWBf = sm1 + 128 * 96;            // 128*64
    float* sBF  = sWBf + 128 * 64;           // 128
    float* sBB  = sBF + 128;                 // 128
    const int br = blockIdx.y;
    const float* Wih = br ? vWih : lWih;
    const float* Whh = br ? vWhh : lWhh;
    const float* bb  = br ? vb   : lb;

    for (int idx = threadIdx.x; idx < 128 * 96; idx += 128) {
        int r = idx / 96, o = idx % 96;
        sWFf[idx] = (o < 64) ? Wih[r * 64 + o] : Whh[r * 32 + (o - 64)];
    }
    for (int idx = threadIdx.x; idx < 128 * 64; idx += 128) {
        int r = idx / 64, o = idx % 64;
        sWBf[idx] = Wih[128 * 64 + r * 64 + o];       // dir 1
    }
    sBF[threadIdx.x] = bb[threadIdx.x];
    sBB[threadIdx.x] = bb[128 + threadIdx.x];
    __syncthreads();

    const u64* sWF = reinterpret_cast<const u64*>(sWFf);
    const u64* sWB = reinterpret_cast<const u64*>(sWBf);
    const unsigned s = blockIdx.x * 256u + threadIdx.x * 2;   // samples s, s+1

    u64 vA[48], vB[48];
    float cA[32], cB[32], hA[32], hB[32];
#pragma unroll
    for (int k = 32; k < 48; ++k) { vA[k] = 0; vB[k] = 0; }
#pragma unroll 1
    for (int j = 0; j < 32; ++j) { cA[j] = 0.f; cB[j] = 0.f; }

    for (int t = 0; t < TT; ++t) {
        const u64* gb = g_l0u + (size_t)(br * TT + t) * 32 * NSAMP;
#pragma unroll
        for (int kp = 0; kp < 32; ++kp) {
            ulonglong2 xv = *reinterpret_cast<const ulonglong2*>(gb + (size_t)kp * NSAMP + s);
            vA[kp] = xv.x; vB[kp] = xv.y;
        }
        cell1<48>(sWF, sBF, vA, vB, cA, cB, hA, hB);
#pragma unroll
        for (int q = 0; q < 16; ++q) {
            vA[32 + q] = pack2(hA[2 * q], hA[2 * q + 1]);
            vB[32 + q] = pack2(hB[2 * q], hB[2 * q + 1]);
        }
    }

#pragma unroll 1
    for (int j = 0; j < 32; ++j)
        *reinterpret_cast<u64*>(g_last + (size_t)(br * 64 + j) * NSAMP + s) = pack2(hA[j], hB[j]);

    // bwd single step: input = t=14 features (still in vA/vB[0..31]), h0=c0=0
#pragma unroll 1
    for (int j = 0; j < 32; ++j) { cA[j] = 0.f; cB[j] = 0.f; }
    cell1<32>(sWB, sBB, vA, vB, cA, cB, hA, hB);
#pragma unroll 1
    for (int j = 0; j < 32; ++j)
        *reinterpret_cast<u64*>(g_last + (size_t)(br * 64 + 32 + j) * NSAMP + s) = pack2(hA[j], hB[j]);
}

// ---------------- Head: argmax masks + FC (full MLP) ----------------
__global__ void __launch_bounds__(128) head_kernel(
    const float* __restrict__ dir,
    const float* __restrict__ lW, const float* __restrict__ lbias,
    const float* __restrict__ vW, const float* __restrict__ vbias,
    float* __restrict__ out)
{
    const int b = blockIdx.x * 128 + threadIdx.x;
    if (b >= BORIG) return;

    const float* di = dir + (size_t)b * 6;
    int am = 0; float mv = di[0];
#pragma unroll
    for (int i = 1; i < 6; ++i) { float x = di[i]; if (x > mv) { mv = x; am = i; } }
    const float m_vor = (am == 1 || am == 4) ? 1.f : 0.f;
    const float m_r   = (am == 0 || am == 5) ? 1.f : 0.f;
    const float m_l   = (am == 2 || am == 3) ? 1.f : 0.f;

    const float* ll = g_last + b;                              // lvl, left half
    const float* lr = g_last + b + BORIG;                      // lvl, right half
    const float* vl = g_last + (size_t)64 * NSAMP + b;         // vor, left
    const float* vr = g_last + (size_t)64 * NSAMP + b + BORIG; // vor, right

    float xr0 = lbias[0], xr1 = lbias[1], xl0 = lbias[0], xl1 = lbias[1];
#pragma unroll
    for (int k = 0; k < 64; ++k) {
        float w0 = lW[k], w1 = lW[64 + k];
        float a = lr[(size_t)k * NSAMP], bb2 = ll[(size_t)k * NSAMP];
        xr0 = fmaf(a, w0, xr0); xr1 = fmaf(a, w1, xr1);
        xl0 = fmaf(bb2, w0, xl0); xl1 = fmaf(bb2, w1, xl1);
    }
    float xv0 = vbias[0], xv1 = vbias[1];
#pragma unroll
    for (int k = 0; k < 64; ++k) {
        float a = vl[(size_t)k * NSAMP];
        xv0 = fmaf(a, vW[k], xv0); xv1 = fmaf(a, vW[128 + k], xv1);
    }
#pragma unroll
    for (int k = 0; k < 64; ++k) {
        float a = vr[(size_t)k * NSAMP];
        xv0 = fmaf(a, vW[64 + k], xv0); xv1 = fmaf(a, vW[192 + k], xv1);
    }
    out[2 * b]     = xr0 * m_r + xl0 * m_l + xv0 * m_vor;
    out[2 * b + 1] = xr1 * m_r + xl1 * m_l + xv1 * m_vor;
}

extern "C" void kernel_launch(void* const* d_in, const int* in_sizes, int n_in,
                              void* d_out, int out_size)
{
    (void)in_sizes; (void)n_in; (void)out_size;
    const float* dir    = (const float*)d_in[0];
    const float* pos    = (const float*)d_in[1];
    const float* lWih0  = (const float*)d_in[2];
    const float* lWhh0  = (const float*)d_in[3];
    const float* lb0    = (const float*)d_in[4];
    const float* lWih1  = (const float*)d_in[5];
    const float* lWhh1  = (const float*)d_in[6];
    const float* lb1    = (const float*)d_in[7];
    const float* vWih0  = (const float*)d_in[8];
    const float* vWhh0  = (const float*)d_in[9];
    const float* vb0    = (const float*)d_in[10];
    const float* vWih1  = (const float*)d_in[11];
    const float* vWhh1  = (const float*)d_in[12];
    const float* vb1    = (const float*)d_in[13];
    const float* lfcW   = (const float*)d_in[14];
    const float* lfcb   = (const float*)d_in[15];
    const float* vfcW   = (const float*)d_in[16];
    const float* vfcb   = (const float*)d_in[17];
    float* out = (float*)d_out;

    const int smem1 = (128 * 96 + 128 * 64 + 256) * 4;   // 82944 B
    cudaFuncSetAttribute(lstm_layer1, cudaFuncAttributeMaxDynamicSharedMemorySize, smem1);

    k_transpose<<<NSAMP / 128, 128>>>(pos);
    lstm_layer0<<<dim3(NSAMP / 512, 2, 2), 128>>>(lWih0, lWhh0, lb0, vWih0, vWhh0, vb0);
    lstm_layer1<<<dim3(NSAMP / 256, 2), 128, smem1>>>(lWih1, lWhh1, lb1, vWih1, vWhh1, vb1);
    head_kernel<<<256, 128>>>(dir, lfcW, lfcb, vfcW, vfcb, out);
}